// round 1
// baseline (speedup 1.0000x reference)
#include <cuda_runtime.h>
#include <cuda_bf16.h>

// Problem constants (fixed by the dataset)
#define T_STEPS 16384
#define BATCH   2048
#define D_PRE   32          // prefetch depth (ring) in scan kernel

// Scratch: precomputed carry-independent term a[t, b], padded by D_PRE steps
// so the prefetch ring can read past the end harmlessly. __device__ globals
// are the allowed scratch mechanism (no cudaMalloc).
__device__ float g_pre[(T_STEPS + D_PRE) * BATCH];

__device__ __forceinline__ float tanh_fast(float x) {
    float y;
    asm("tanh.approx.f32 %0, %1;" : "=f"(y) : "f"(x));
    return y;
}

// ---------------------------------------------------------------------------
// Pass 1: a[t,b] = w0*x0 + w1*x1 + (w2+1)*x2   (skip-connection folded into w2)
// Vectorized: each thread handles 4 (t,b) triples = 3 float4 loads, 1 float4 store.
// ---------------------------------------------------------------------------
__global__ void __launch_bounds__(256) precompute_kernel(
    const float* __restrict__ x,     // [T, B, 3]
    const float* __restrict__ w,     // [1, 5]
    float* __restrict__ a)           // [T+pad, B]
{
    const float w0 = w[0];
    const float w1 = w[1];
    const float w2 = w[2] + 1.0f;    // +1 = skip of last input tap

    long i = (long)blockIdx.x * blockDim.x + threadIdx.x;   // quad index
    const long N4 = (long)T_STEPS * BATCH / 4;
    if (i >= N4) return;

    const float4* in4 = (const float4*)x;
    float4 p = in4[3 * i + 0];
    float4 q = in4[3 * i + 1];
    float4 r = in4[3 * i + 2];

    float4 o;
    o.x = fmaf(w0, p.x, fmaf(w1, p.y, w2 * p.z));
    o.y = fmaf(w0, p.w, fmaf(w1, q.x, w2 * q.y));
    o.z = fmaf(w0, q.z, fmaf(w1, q.w, w2 * r.x));
    o.w = fmaf(w0, r.y, fmaf(w1, r.z, w2 * r.w));

    ((float4*)a)[i] = o;
}

// ---------------------------------------------------------------------------
// Pass 2: sequential nonlinear scan, one thread per batch lane.
// Critical path per step: FMA(4) + MUFU.TANH(16) ~= 20 cycles.
// Depth-32 register prefetch ring keeps DRAM latency fully off the chain:
//   32 outstanding LDGs/thread (< M_max ~55), 640 cycles of cover (> 577).
// ---------------------------------------------------------------------------
__global__ void __launch_bounds__(32) scan_kernel(
    const float* __restrict__ a,      // [T+pad, B]
    const float* __restrict__ carry,  // [B, 2]
    const float* __restrict__ w,      // [1, 5]
    float* __restrict__ out)          // [T, B]
{
    const int b = blockIdx.x * blockDim.x + threadIdx.x;   // 0..BATCH-1

    const float w3 = w[3];
    const float w4 = w[4];

    float o1 = carry[2 * b + 0];   // o_{t-1}
    float o2 = carry[2 * b + 1];   // o_{t-2}

    const float* ap = a + b;
    float*       op = out + b;

    float buf[D_PRE];

    // Prologue: fill the ring for t = 0 .. D_PRE-1
#pragma unroll
    for (int i = 0; i < D_PRE; i++)
        buf[i] = ap[i * BATCH];
    ap += D_PRE * BATCH;

    for (int t = 0; t < T_STEPS; t += D_PRE) {
#pragma unroll
        for (int i = 0; i < D_PRE; i++) {
            float av = buf[i];
            // Prefetch step t + D_PRE + i (padded region covers the tail).
            buf[i] = ap[i * BATCH];

            float s = fmaf(w4, o2, av);     // off-chain: o_{t-2} ready a step early
            s = fmaf(w3, o1, s);            // chain: FMA
            float o = tanh_fast(s);         // chain: MUFU.TANH
            op[i * BATCH] = o;

            o2 = o1;
            o1 = o;
        }
        ap += D_PRE * BATCH;
        op += D_PRE * BATCH;
    }
}

// ---------------------------------------------------------------------------
// Launch
// ---------------------------------------------------------------------------
extern "C" void kernel_launch(void* const* d_in, const int* in_sizes, int n_in,
                              void* d_out, int out_size)
{
    const float* inputs  = (const float*)d_in[0];   // [T, B, 3]
    const float* carry   = (const float*)d_in[1];   // [B, 2]
    const float* weights = (const float*)d_in[2];   // [1, 5]
    float* out = (float*)d_out;                     // [T, B, 1]

    float* pre = nullptr;
    cudaGetSymbolAddress((void**)&pre, g_pre);

    {
        const long N4 = (long)T_STEPS * BATCH / 4;
        const int threads = 256;
        const int blocks = (int)((N4 + threads - 1) / threads);
        precompute_kernel<<<blocks, threads>>>(inputs, weights, pre);
    }

    {
        // 64 blocks x 32 threads: one warp per block, spread across SMs.
        scan_kernel<<<BATCH / 32, 32>>>(pre, carry, weights, out);
    }
}